// round 8
// baseline (speedup 1.0000x reference)
#include <cuda_runtime.h>
#include <cuda_bf16.h>
#include <cstdint>

#define M_Q 4096
#define KDIM 512
#define NDB 50000
#define NSEG 8
#define SEGROWS 6272
#define NPAD (NSEG*SEGROWS)
#define BM 128
#define BN 64
#define NCHUNKS (SEGROWS/BN)    // 98
#define NCAND 16
#define NPRE 32
#define ROWB 528                // 512B + 16B pad: lane stride 132 words == 4 mod 32

#define QSC  23.090909f         // 127/5.5
#define DEQ2 (2.0f/(QSC*QSC))

#define SCP 68                  // scores pitch (words)
#define SM_A   0                // 128 x 528 = 67584
#define SM_B0  67584            // 64 x 528 = 33792
#define SM_B1  101376
#define SM_SC  135168           // scores[128][68] fp32 = 34816
#define SM_NRM 169984           // norm staging [2][64] fp32 = 512
#define SMEM_SC_TOTAL 170496

__device__ int8_t g_Xq[(size_t)M_Q*KDIM];
__device__ int8_t g_DBq[(size_t)NPAD*KDIM];
__device__ float g_dbnorm[NPAD];
__device__ float g_cv[(size_t)M_Q*NSEG*NCAND];
__device__ int   g_ci[(size_t)M_Q*NSEG*NCAND];

__device__ __forceinline__ unsigned smem_u32(const void* p) {
    unsigned a;
    asm("{ .reg .u64 t; cvta.to.shared.u64 t, %1; cvt.u32.u64 %0, t; }"
        : "=r"(a) : "l"(p));
    return a;
}
__device__ __forceinline__ void cp16(unsigned dsts, const void* src) {
    asm volatile("cp.async.cg.shared.global [%0], [%1], 16;\n" :: "r"(dsts), "l"(src));
}
__device__ __forceinline__ int dp4(unsigned a, unsigned b, int c) {
    return __dp4a((int)a, (int)b, c);
}

// ---------------- prep: fp32 -> int8 (scale 127/5.5) + exact fp32 norms ----------------
__global__ void conv_x_kernel(const float* __restrict__ x) {
    int i = blockIdx.x*blockDim.x + threadIdx.x;
    if (i < M_Q*KDIM) {
        float v = fminf(fmaxf(x[i], -5.5f), 5.5f);
        g_Xq[i] = (int8_t)__float2int_rn(v * QSC);
    }
}

__global__ void conv_db_kernel(const float* __restrict__ db) {
    int r = blockIdx.x;
    int tid = threadIdx.x;      // 128
    __shared__ float wsum[4];
    if (r < NDB) {
        const float* row = db + (size_t)r*KDIM;
        float acc = 0.f;
        for (int k = tid; k < KDIM; k += 128) {
            float v = row[k];
            acc += v*v;
            float c = fminf(fmaxf(v, -5.5f), 5.5f);
            g_DBq[(size_t)r*KDIM + k] = (int8_t)__float2int_rn(c * QSC);
        }
        #pragma unroll
        for (int o = 16; o; o >>= 1) acc += __shfl_xor_sync(0xffffffffu, acc, o);
        if ((tid & 31) == 0) wsum[tid >> 5] = acc;
        __syncthreads();
        if (tid == 0) g_dbnorm[r] = wsum[0]+wsum[1]+wsum[2]+wsum[3];
    } else {
        for (int k = tid; k < KDIM; k += 128)
            g_DBq[(size_t)r*KDIM + k] = 0;
        if (tid == 0) g_dbnorm[r] = __int_as_float(0x7f800000);
    }
}

// ---------------- fused dp4a score + top-16 ----------------
__device__ __forceinline__ void select64(const float* srow, const float* nb,
                                         int base, float* tv, int* ti) {
    float worst = tv[NCAND-1];
    #pragma unroll
    for (int j = 0; j < 64; ++j) {
        float v = nb[j] - DEQ2*srow[j];
        if (v < worst) {
            int p = NCAND-1;
            while (p > 0 && tv[p-1] > v) { tv[p] = tv[p-1]; ti[p] = ti[p-1]; --p; }
            tv[p] = v; ti[p] = base + j;
            worst = tv[NCAND-1];
        }
    }
}

__global__ __launch_bounds__(256, 1)
void score_topk_kernel() {
    extern __shared__ char sm[];
    const int tid = threadIdx.x;
    const int w = tid >> 5, lane = tid & 31;   // warp w owns cols [8w, 8w+8)
    const int m0 = blockIdx.x * BM;
    const int segbase = blockIdx.y * SEGROWS;
    const unsigned sbase = smem_u32(sm);
    float* scS  = (float*)(sm + SM_SC);
    float* nrmS = (float*)(sm + SM_NRM);

    // prologue: A tile (128x512 int8, resident) + B chunk 0
    for (int i = tid; i < BM*32; i += 256) {
        int r = i >> 5, c16 = i & 31;
        cp16(sbase + SM_A + r*ROWB + c16*16, g_Xq + (size_t)(m0 + r)*KDIM + c16*16);
    }
    for (int i = tid; i < BN*32; i += 256) {
        int r = i >> 5, c16 = i & 31;
        cp16(sbase + SM_B0 + r*ROWB + c16*16, g_DBq + (size_t)(segbase + r)*KDIM + c16*16);
    }
    asm volatile("cp.async.commit_group;\n" ::: "memory");
    if (tid < 64) nrmS[tid] = __ldg(&g_dbnorm[segbase + tid]);   // chunk0 -> slot0

    float tv[NCAND]; int ti[NCAND];
    #pragma unroll
    for (int i = 0; i < NCAND; ++i) { tv[i] = __int_as_float(0x7f800000); ti[i] = -1; }

    const char* Ab = sm + SM_A + lane*ROWB;      // rows lane + 32*i
    const char* Bw0 = sm + SM_B0 + w*8*ROWB;     // rows 8w + j
    const char* Bw1 = sm + SM_B1 + w*8*ROWB;

    for (int c = 0; c < NCHUNKS; ++c) {
        asm volatile("cp.async.wait_group 0;\n" ::: "memory");
        __syncthreads();          // B[c] ready; scores[c-1] visible

        if (c + 1 < NCHUNKS) {    // prefetch B[c+1]: DMA rides under compute
            unsigned nxt = sbase + ((c & 1) ? SM_B0 : SM_B1);
            const int8_t* src = g_DBq + (size_t)(segbase + (c+1)*BN)*KDIM;
            for (int i = tid; i < BN*32; i += 256) {
                int r = i >> 5, c16 = i & 31;
                cp16(nxt + r*ROWB + c16*16, src + (size_t)r*KDIM + c16*16);
            }
            asm volatile("cp.async.commit_group;\n" ::: "memory");
        }

        int acc[4][8];
        #pragma unroll
        for (int i = 0; i < 4; ++i)
            #pragma unroll
            for (int j = 0; j < 8; ++j) acc[i][j] = 0;

        const char* Bc = (c & 1) ? Bw1 : Bw0;
        #pragma unroll 2
        for (int ks = 0; ks < 32; ++ks) {       // 32 x k16 = K512
            uint4 bv[8];
            #pragma unroll
            for (int j = 0; j < 8; ++j)
                bv[j] = *(const uint4*)(Bc + j*ROWB + ks*16);    // warp-uniform
            #pragma unroll
            for (int i = 0; i < 4; ++i) {
                uint4 av = *(const uint4*)(Ab + i*32*ROWB + ks*16);
                #pragma unroll
                for (int j = 0; j < 8; ++j) {
                    acc[i][j] = dp4(av.x, bv[j].x, acc[i][j]);
                    acc[i][j] = dp4(av.y, bv[j].y, acc[i][j]);
                    acc[i][j] = dp4(av.z, bv[j].z, acc[i][j]);
                    acc[i][j] = dp4(av.w, bv[j].w, acc[i][j]);
                }
            }
        }

        // select chunk c-1 while epilogue pending
        if (c > 0 && tid < 128)
            select64(scS + tid*SCP, nrmS + ((c-1) & 1)*64,
                     segbase + (c-1)*BN, tv, ti);
        __syncthreads();          // selection done; scores buffer free

        #pragma unroll
        for (int i = 0; i < 4; ++i) {        // row = lane + 32*i, cols 8w..8w+7
            float4 f0 = make_float4((float)acc[i][0], (float)acc[i][1],
                                    (float)acc[i][2], (float)acc[i][3]);
            float4 f1 = make_float4((float)acc[i][4], (float)acc[i][5],
                                    (float)acc[i][6], (float)acc[i][7]);
            float* dst = scS + (lane + 32*i)*SCP + w*8;
            *(float4*)dst = f0;
            *(float4*)(dst + 4) = f1;
        }
        if (c >= 1 && tid < 64)   // stage norms for chunk c -> slot c&1
            nrmS[(c & 1)*64 + tid] = __ldg(&g_dbnorm[segbase + c*BN + tid]);
    }
    __syncthreads();
    if (tid < 128) {
        select64(scS + tid*SCP, nrmS + ((NCHUNKS-1) & 1)*64,
                 segbase + (NCHUNKS-1)*BN, tv, ti);
        size_t base = ((size_t)(m0 + tid)*NSEG + blockIdx.y)*NCAND;
        #pragma unroll
        for (int i = 0; i < NCAND; ++i) { g_cv[base + i] = tv[i]; g_ci[base + i] = ti[i]; }
    }
}

// ---------------- LLE (unchanged, proven: exact fp32 rescore of top-32) ----------------
__global__ __launch_bounds__(128)
void lle_kernel(const float* __restrict__ x, const float* __restrict__ db,
                float* __restrict__ out) {
    __shared__ float xs[512];
    __shared__ float nb[10*520];
    __shared__ float cv[128];
    __shared__ int   ci[128];
    __shared__ int   psel[NPRE];
    __shared__ float pd[NPRE];
    __shared__ float G[9][10];
    __shared__ float w[9];
    __shared__ int   sel[10];

    const int q = blockIdx.x, tid = threadIdx.x;
    const int warp = tid >> 5, lane = tid & 31;
    size_t cb = (size_t)q*NSEG*NCAND;
    cv[tid] = g_cv[cb + tid];
    ci[tid] = g_ci[cb + tid];
    for (int n = tid; n < 512; n += 128) xs[n] = x[(size_t)q*512 + n];
    __syncthreads();

    if (tid == 0) {   // approx preselect top-NPRE of 128
        float bv[NPRE]; int bi[NPRE];
        #pragma unroll
        for (int i = 0; i < NPRE; ++i) { bv[i] = __int_as_float(0x7f800000); bi[i] = 0x7fffffff; }
        for (int c = 0; c < 128; ++c) {
            float v = cv[c]; int id = ci[c];
            if (v < bv[NPRE-1]) {
                int p = NPRE-1;
                while (p > 0 && bv[p-1] > v) { bv[p] = bv[p-1]; bi[p] = bi[p-1]; --p; }
                bv[p] = v; bi[p] = id;
            }
        }
        #pragma unroll
        for (int i = 0; i < NPRE; ++i) psel[i] = bi[i];
    }
    __syncthreads();

    for (int c = warp*8; c < warp*8 + 8; ++c) {   // exact fp32 rescore
        const float* row = db + (size_t)psel[c]*512;
        float acc = 0.f;
        #pragma unroll
        for (int j = 0; j < 16; ++j) {
            int n = lane + 32*j;
            float v = row[n] - xs[n];
            acc = fmaf(v, v, acc);
        }
        #pragma unroll
        for (int o = 16; o; o >>= 1) acc += __shfl_xor_sync(0xffffffffu, acc, o);
        if (lane == 0) pd[c] = acc;
    }
    __syncthreads();

    if (tid == 0) {   // exact ordered top-10 (d asc, idx asc)
        float bv[10]; int bi[10];
        #pragma unroll
        for (int i = 0; i < 10; ++i) { bv[i] = __int_as_float(0x7f800000); bi[i] = 0x7fffffff; }
        for (int c = 0; c < NPRE; ++c) {
            float v = pd[c]; int id = psel[c];
            if (v < bv[9] || (v == bv[9] && id < bi[9])) {
                int p = 9;
                while (p > 0 && (bv[p-1] > v || (bv[p-1] == v && bi[p-1] > id))) {
                    bv[p] = bv[p-1]; bi[p] = bi[p-1]; --p;
                }
                bv[p] = v; bi[p] = id;
            }
        }
        #pragma unroll
        for (int i = 0; i < 10; ++i) sel[i] = bi[i];
    }
    __syncthreads();

    for (int r = 0; r < 10; ++r) {
        const float* row = db + (size_t)sel[r]*512;
        for (int n = tid; n < 512; n += 128) nb[r*520 + n] = row[n];
    }
    __syncthreads();

    if (tid < 90) {
        float accv = 0.f;
        if (tid < 81) {
            int i = tid / 9, j = tid % 9;
            const float* ai = nb + (i+1)*520;
            const float* aj = nb + (j+1)*520;
            for (int n = 0; n < 512; ++n) {
                float f0 = nb[n];
                accv += (ai[n]-f0)*(aj[n]-f0);
            }
            G[i][j] = accv;
        } else {
            int i = tid - 81;
            const float* ai = nb + (i+1)*520;
            for (int n = 0; n < 512; ++n) {
                float f0 = nb[n];
                accv += (ai[n]-f0)*(xs[n]-f0);
            }
            G[i][9] = accv;
        }
    }
    __syncthreads();

    if (tid == 0) {
        for (int k = 0; k < 9; ++k) {
            int p = k;
            for (int r = k+1; r < 9; ++r)
                if (fabsf(G[r][k]) > fabsf(G[p][k])) p = r;
            if (p != k)
                for (int c = k; c < 10; ++c) {
                    float t = G[k][c]; G[k][c] = G[p][c]; G[p][c] = t;
                }
            float inv = 1.f / G[k][k];
            for (int r = k+1; r < 9; ++r) {
                float f = G[r][k] * inv;
                for (int c = k; c < 10; ++c) G[r][c] -= f*G[k][c];
            }
        }
        for (int k = 8; k >= 0; --k) {
            float s = G[k][9];
            for (int c = k+1; c < 9; ++c) s -= G[k][c]*w[c];
            w[k] = s / G[k][k];
        }
    }
    __syncthreads();

    float w0 = 1.f;
    #pragma unroll
    for (int k = 0; k < 9; ++k) w0 -= w[k];
    for (int n = tid; n < 512; n += 128) {
        float fuse = w0 * nb[n];
        #pragma unroll
        for (int k = 0; k < 9; ++k) fuse += w[k]*nb[(k+1)*520 + n];
        out[(size_t)q*512 + n] = 0.2f*xs[n] + 0.8f*fuse;
    }
}

extern "C" void kernel_launch(void* const* d_in, const int* in_sizes, int n_in,
                              void* d_out, int out_size) {
    const float* x  = (const float*)d_in[0];
    const float* db = (const float*)d_in[1];
    float* out = (float*)d_out;

    cudaFuncSetAttribute(score_topk_kernel,
        cudaFuncAttributeMaxDynamicSharedMemorySize, SMEM_SC_TOTAL);

    conv_x_kernel<<<(M_Q*KDIM + 255)/256, 256>>>(x);
    conv_db_kernel<<<NPAD, 128>>>(db);
    score_topk_kernel<<<dim3(M_Q/BM, NSEG), 256, SMEM_SC_TOTAL>>>();
    lle_kernel<<<M_Q, 128>>>(x, db, out);
}

// round 9
// speedup vs baseline: 1.2712x; 1.2712x over previous
#include <cuda_runtime.h>
#include <cuda_bf16.h>
#include <cstdint>

#define M_Q 4096
#define KDIM 512
#define NDB 50000
#define NSEG 8
#define SEGROWS 6272
#define NPAD (NSEG*SEGROWS)
#define BM 128
#define BN 64
#define NCHUNKS (SEGROWS/BN)    // 98
#define NCAND 16
#define NPRE 32
#define ROWB 528                // 512B + 16B pad

#define QSC  23.090909f         // 127/5.5
#define DEQ2 (2.0f/(QSC*QSC))

#define SCP 68
#define SM_A   0                // 128 x 528 = 67584
#define SM_B0  67584            // 64 x 528 = 33792
#define SM_B1  101376
#define SM_SC  135168           // scores[128][68] fp32 = 34816
#define SM_NRM 169984           // [2][64] fp32
#define SMEM_SC_TOTAL 170496

__device__ int8_t g_Xq[(size_t)M_Q*KDIM];
__device__ int8_t g_DBq[(size_t)NPAD*KDIM];
__device__ float g_dbnorm[NPAD];
__device__ float g_cv[(size_t)M_Q*NSEG*NCAND];
__device__ int   g_ci[(size_t)M_Q*NSEG*NCAND];

__device__ __forceinline__ unsigned smem_u32(const void* p) {
    unsigned a;
    asm("{ .reg .u64 t; cvta.to.shared.u64 t, %1; cvt.u32.u64 %0, t; }"
        : "=r"(a) : "l"(p));
    return a;
}
__device__ __forceinline__ void cp16(unsigned dsts, const void* src) {
    asm volatile("cp.async.cg.shared.global [%0], [%1], 16;\n" :: "r"(dsts), "l"(src));
}
__device__ __forceinline__ void ldsm4(unsigned& r0, unsigned& r1, unsigned& r2,
                                      unsigned& r3, unsigned addr) {
    asm volatile("ldmatrix.sync.aligned.m8n8.x4.shared.b16 {%0,%1,%2,%3}, [%4];"
                 : "=r"(r0), "=r"(r1), "=r"(r2), "=r"(r3) : "r"(addr));
}
__device__ __forceinline__ void imma16832(int* c,
    unsigned a0, unsigned a1, unsigned a2, unsigned a3, unsigned b0, unsigned b1) {
    asm volatile("mma.sync.aligned.m16n8k32.row.col.s32.s8.s8.s32 "
        "{%0,%1,%2,%3}, {%4,%5,%6,%7}, {%8,%9}, {%0,%1,%2,%3};\n"
        : "+r"(c[0]), "+r"(c[1]), "+r"(c[2]), "+r"(c[3])
        : "r"(a0), "r"(a1), "r"(a2), "r"(a3), "r"(b0), "r"(b1));
}
__device__ __forceinline__ int dp4(unsigned a, unsigned b, int c) {
    return __dp4a((int)a, (int)b, c);
}

// ---------------- prep ----------------
__global__ void conv_x_kernel(const float* __restrict__ x) {
    int i = blockIdx.x*blockDim.x + threadIdx.x;
    if (i < M_Q*KDIM) {
        float v = fminf(fmaxf(x[i], -5.5f), 5.5f);
        g_Xq[i] = (int8_t)__float2int_rn(v * QSC);
    }
}

__global__ void conv_db_kernel(const float* __restrict__ db) {
    int r = blockIdx.x;
    int tid = threadIdx.x;      // 128
    __shared__ float wsum[4];
    if (r < NDB) {
        const float* row = db + (size_t)r*KDIM;
        float acc = 0.f;
        for (int k = tid; k < KDIM; k += 128) {
            float v = row[k];
            acc += v*v;
            float c = fminf(fmaxf(v, -5.5f), 5.5f);
            g_DBq[(size_t)r*KDIM + k] = (int8_t)__float2int_rn(c * QSC);
        }
        #pragma unroll
        for (int o = 16; o; o >>= 1) acc += __shfl_xor_sync(0xffffffffu, acc, o);
        if ((tid & 31) == 0) wsum[tid >> 5] = acc;
        __syncthreads();
        if (tid == 0) g_dbnorm[r] = wsum[0]+wsum[1]+wsum[2]+wsum[3];
    } else {
        for (int k = tid; k < KDIM; k += 128)
            g_DBq[(size_t)r*KDIM + k] = 0;
        if (tid == 0) g_dbnorm[r] = __int_as_float(0x7f800000);
    }
}

// ---------------- hybrid score: imma warps (cols 0-31) + dp4a warps (cols 32-63) ----------------
__device__ __forceinline__ void select64(const float* srow, const float* nb,
                                         int base, float* tv, int* ti) {
    float worst = tv[NCAND-1];
    #pragma unroll
    for (int j = 0; j < 64; ++j) {
        float v = nb[j] - DEQ2*srow[j];
        if (v < worst) {
            int p = NCAND-1;
            while (p > 0 && tv[p-1] > v) { tv[p] = tv[p-1]; ti[p] = ti[p-1]; --p; }
            tv[p] = v; ti[p] = base + j;
            worst = tv[NCAND-1];
        }
    }
}

__global__ __launch_bounds__(512, 1)
void score_topk_kernel(int seg0) {
    extern __shared__ char sm[];
    const int tid = threadIdx.x;
    const int warp = tid >> 5, lane = tid & 31;
    const int m0 = blockIdx.x * BM;
    const int seg = seg0 + blockIdx.y;
    const int segbase = seg * SEGROWS;
    const unsigned sbase = smem_u32(sm);
    float* scS  = (float*)(sm + SM_SC);
    float* nrmS = (float*)(sm + SM_NRM);

    // prologue: A tile + B chunk 0
    for (int i = tid; i < BM*32; i += 512) {
        int r = i >> 5, c16 = i & 31;
        cp16(sbase + SM_A + r*ROWB + c16*16, g_Xq + (size_t)(m0 + r)*KDIM + c16*16);
    }
    for (int i = tid; i < BN*32; i += 512) {
        int r = i >> 5, c16 = i & 31;
        cp16(sbase + SM_B0 + r*ROWB + c16*16, g_DBq + (size_t)(segbase + r)*KDIM + c16*16);
    }
    asm volatile("cp.async.commit_group;\n" ::: "memory");
    if (tid < 64) nrmS[tid] = __ldg(&g_dbnorm[segbase + tid]);

    float tv[NCAND]; int ti[NCAND];
    #pragma unroll
    for (int i = 0; i < NCAND; ++i) { tv[i] = __int_as_float(0x7f800000); ti[i] = -1; }

    // imma warps 0-7: wm in 0..3, wn in 0..1 (cols 0-31)
    const int wm = warp >> 1, wn = warp & 1;
    const unsigned aBase = sbase + SM_A
        + (unsigned)((wm*32 + (lane & 15))*ROWB + (lane >> 4)*16);
    const unsigned bRow = (unsigned)(
        (wn*16 + ((lane >> 4) << 3) + (lane & 7))*ROWB + ((lane >> 3) & 1)*16);
    // dp4a warps 8-15: q = warp-8 owns cols 32+4q..+4
    const int q = warp - 8;
    const char* Ab = sm + SM_A + lane*ROWB;

    for (int c = 0; c < NCHUNKS; ++c) {
        asm volatile("cp.async.wait_group 0;\n" ::: "memory");
        __syncthreads();

        if (c + 1 < NCHUNKS) {
            unsigned nxt = sbase + ((c & 1) ? SM_B0 : SM_B1);
            const int8_t* src = g_DBq + (size_t)(segbase + (c+1)*BN)*KDIM;
            for (int i = tid; i < BN*32; i += 512) {
                int r = i >> 5, c16 = i & 31;
                cp16(nxt + r*ROWB + c16*16, src + (size_t)r*KDIM + c16*16);
            }
            asm volatile("cp.async.commit_group;\n" ::: "memory");
        }

        const unsigned Bsm = (c & 1) ? SM_B1 : SM_B0;

        if (warp < 8) {
            // ---- tensor engine: mma.sync, 32 rows x 16 cols per warp ----
            int acc[2][2][4];
            #pragma unroll
            for (int mt = 0; mt < 2; ++mt)
                #pragma unroll
                for (int nt = 0; nt < 2; ++nt)
                    #pragma unroll
                    for (int e = 0; e < 4; ++e) acc[mt][nt][e] = 0;

            const unsigned bBase = sbase + Bsm + bRow;
            #pragma unroll 8
            for (int ks = 0; ks < 16; ++ks) {
                unsigned a0[4], a1[4], b[4];
                ldsm4(a0[0], a0[1], a0[2], a0[3], aBase + ks*32);
                ldsm4(a1[0], a1[1], a1[2], a1[3], aBase + 16*ROWB + ks*32);
                ldsm4(b[0], b[1], b[2], b[3], bBase + ks*32);
                imma16832(acc[0][0], a0[0], a0[1], a0[2], a0[3], b[0], b[1]);
                imma16832(acc[0][1], a0[0], a0[1], a0[2], a0[3], b[2], b[3]);
                imma16832(acc[1][0], a1[0], a1[1], a1[2], a1[3], b[0], b[1]);
                imma16832(acc[1][1], a1[0], a1[1], a1[2], a1[3], b[2], b[3]);
            }

            if (c > 0 && tid < 128)
                select64(scS + tid*SCP, nrmS + ((c-1) & 1)*64,
                         segbase + (c-1)*BN, tv, ti);
            __syncthreads();

            #pragma unroll
            for (int mt = 0; mt < 2; ++mt)
                #pragma unroll
                for (int nt = 0; nt < 2; ++nt)
                    #pragma unroll
                    for (int e = 0; e < 4; ++e) {
                        int row = wm*32 + mt*16 + (lane >> 2) + ((e >> 1) << 3);
                        int col = wn*16 + nt*8 + ((lane & 3) << 1) + (e & 1);
                        scS[row*SCP + col] = (float)acc[mt][nt][e];
                    }
        } else {
            // ---- fma engine: dp4a, 4 rows x 4 cols per thread ----
            int acc[4][4];
            #pragma unroll
            for (int i = 0; i < 4; ++i)
                #pragma unroll
                for (int j = 0; j < 4; ++j) acc[i][j] = 0;

            const char* Bd = sm + Bsm + (32 + 4*q)*ROWB;
            #pragma unroll 4
            for (int ks = 0; ks < 32; ++ks) {
                uint4 bv[4];
                #pragma unroll
                for (int j = 0; j < 4; ++j)
                    bv[j] = *(const uint4*)(Bd + j*ROWB + ks*16);   // warp-uniform
                #pragma unroll
                for (int i = 0; i < 4; ++i) {
                    uint4 av = *(const uint4*)(Ab + i*32*ROWB + ks*16);
                    #pragma unroll
                    for (int j = 0; j < 4; ++j) {
                        acc[i][j] = dp4(av.x, bv[j].x, acc[i][j]);
                        acc[i][j] = dp4(av.y, bv[j].y, acc[i][j]);
                        acc[i][j] = dp4(av.z, bv[j].z, acc[i][j]);
                        acc[i][j] = dp4(av.w, bv[j].w, acc[i][j]);
                    }
                }
            }
            __syncthreads();     // pairs with imma side's post-select barrier

            #pragma unroll
            for (int i = 0; i < 4; ++i) {
                float4 f = make_float4((float)acc[i][0], (float)acc[i][1],
                                       (float)acc[i][2], (float)acc[i][3]);
                *(float4*)(scS + (lane + 32*i)*SCP + 32 + 4*q) = f;
            }
        }

        if (c >= 1 && tid < 64)
            nrmS[(c & 1)*64 + tid] = __ldg(&g_dbnorm[segbase + c*BN + tid]);
    }
    __syncthreads();
    if (tid < 128) {
        select64(scS + tid*SCP, nrmS + ((NCHUNKS-1) & 1)*64,
                 segbase + (NCHUNKS-1)*BN, tv, ti);
        size_t base = ((size_t)(m0 + tid)*NSEG + seg)*NCAND;
        #pragma unroll
        for (int i = 0; i < NCAND; ++i) { g_cv[base + i] = tv[i]; g_ci[base + i] = ti[i]; }
    }
}

// ---------------- LLE (unchanged, proven) ----------------
__global__ __launch_bounds__(128)
void lle_kernel(const float* __restrict__ x, const float* __restrict__ db,
                float* __restrict__ out) {
    __shared__ float xs[512];
    __shared__ float nb[10*520];
    __shared__ float cv[128];
    __shared__ int   ci[128];
    __shared__ int   psel[NPRE];
    __shared__ float pd[NPRE];
    __shared__ float G[9][10];
    __shared__ float w[9];
    __shared__ int   sel[10];

    const int q = blockIdx.x, tid = threadIdx.x;
    const int warp = tid >> 5, lane = tid & 31;
    size_t cb = (size_t)q*NSEG*NCAND;
    cv[tid] = g_cv[cb + tid];
    ci[tid] = g_ci[cb + tid];
    for (int n = tid; n < 512; n += 128) xs[n] = x[(size_t)q*512 + n];
    __syncthreads();

    if (tid == 0) {
        float bv[NPRE]; int bi[NPRE];
        #pragma unroll
        for (int i = 0; i < NPRE; ++i) { bv[i] = __int_as_float(0x7f800000); bi[i] = 0x7fffffff; }
        for (int c = 0; c < 128; ++c) {
            float v = cv[c]; int id = ci[c];
            if (v < bv[NPRE-1]) {
                int p = NPRE-1;
                while (p > 0 && bv[p-1] > v) { bv[p] = bv[p-1]; bi[p] = bi[p-1]; --p; }
                bv[p] = v; bi[p] = id;
            }
        }
        #pragma unroll
        for (int i = 0; i < NPRE; ++i) psel[i] = bi[i];
    }
    __syncthreads();

    for (int c = warp*8; c < warp*8 + 8; ++c) {
        const float* row = db + (size_t)psel[c]*512;
        float acc = 0.f;
        #pragma unroll
        for (int j = 0; j < 16; ++j) {
            int n = lane + 32*j;
            float v = row[n] - xs[n];
            acc = fmaf(v, v, acc);
        }
        #pragma unroll
        for (int o = 16; o; o >>= 1) acc += __shfl_xor_sync(0xffffffffu, acc, o);
        if (lane == 0) pd[c] = acc;
    }
    __syncthreads();

    if (tid == 0) {
        float bv[10]; int bi[10];
        #pragma unroll
        for (int i = 0; i < 10; ++i) { bv[i] = __int_as_float(0x7f800000); bi[i] = 0x7fffffff; }
        for (int c = 0; c < NPRE; ++c) {
            float v = pd[c]; int id = psel[c];
            if (v < bv[9] || (v == bv[9] && id < bi[9])) {
                int p = 9;
                while (p > 0 && (bv[p-1] > v || (bv[p-1] == v && bi[p-1] > id))) {
                    bv[p] = bv[p-1]; bi[p] = bi[p-1]; --p;
                }
                bv[p] = v; bi[p] = id;
            }
        }
        #pragma unroll
        for (int i = 0; i < 10; ++i) sel[i] = bi[i];
    }
    __syncthreads();

    for (int r = 0; r < 10; ++r) {
        const float* row = db + (size_t)sel[r]*512;
        for (int n = tid; n < 512; n += 128) nb[r*520 + n] = row[n];
    }
    __syncthreads();

    if (tid < 90) {
        float accv = 0.f;
        if (tid < 81) {
            int i = tid / 9, j = tid % 9;
            const float* ai = nb + (i+1)*520;
            const float* aj = nb + (j+1)*520;
            for (int n = 0; n < 512; ++n) {
                float f0 = nb[n];
                accv += (ai[n]-f0)*(aj[n]-f0);
            }
            G[i][j] = accv;
        } else {
            int i = tid - 81;
            const float* ai = nb + (i+1)*520;
            for (int n = 0; n < 512; ++n) {
                float f0 = nb[n];
                accv += (ai[n]-f0)*(xs[n]-f0);
            }
            G[i][9] = accv;
        }
    }
    __syncthreads();

    if (tid == 0) {
        for (int k = 0; k < 9; ++k) {
            int p = k;
            for (int r = k+1; r < 9; ++r)
                if (fabsf(G[r][k]) > fabsf(G[p][k])) p = r;
            if (p != k)
                for (int c = k; c < 10; ++c) {
                    float t = G[k][c]; G[k][c] = G[p][c]; G[p][c] = t;
                }
            float inv = 1.f / G[k][k];
            for (int r = k+1; r < 9; ++r) {
                float f = G[r][k] * inv;
                for (int c = k; c < 10; ++c) G[r][c] -= f*G[k][c];
            }
        }
        for (int k = 8; k >= 0; --k) {
            float s = G[k][9];
            for (int c = k+1; c < 9; ++c) s -= G[k][c]*w[c];
            w[k] = s / G[k][k];
        }
    }
    __syncthreads();

    float w0 = 1.f;
    #pragma unroll
    for (int k = 0; k < 9; ++k) w0 -= w[k];
    for (int n = tid; n < 512; n += 128) {
        float fuse = w0 * nb[n];
        #pragma unroll
        for (int k = 0; k < 9; ++k) fuse += w[k]*nb[(k+1)*520 + n];
        out[(size_t)q*512 + n] = 0.2f*xs[n] + 0.8f*fuse;
    }
}

extern "C" void kernel_launch(void* const* d_in, const int* in_sizes, int n_in,
                              void* d_out, int out_size) {
    const float* x  = (const float*)d_in[0];
    const float* db = (const float*)d_in[1];
    float* out = (float*)d_out;

    cudaFuncSetAttribute(score_topk_kernel,
        cudaFuncAttributeMaxDynamicSharedMemorySize, SMEM_SC_TOTAL);

    conv_x_kernel<<<(M_Q*KDIM + 255)/256, 256>>>(x);
    conv_db_kernel<<<NPAD, 128>>>(db);
    score_topk_kernel<<<dim3(M_Q/BM, NSEG/2), 512, SMEM_SC_TOTAL>>>(0);
    score_topk_kernel<<<dim3(M_Q/BM, NSEG/2), 512, SMEM_SC_TOTAL>>>(4);  // 4th launch -> ncu
    lle_kernel<<<M_Q, 128>>>(x, db, out);
}

// round 11
// speedup vs baseline: 1.9109x; 1.5033x over previous
#include <cuda_runtime.h>
#include <cuda_bf16.h>
#include <cstdint>

#define M_Q 4096
#define KDIM 512
#define NDB 50000
#define NSEG 8
#define SEGROWS 6272
#define NPAD (NSEG*SEGROWS)
#define BM 64
#define BN 64
#define NCHUNKS (SEGROWS/BN)    // 98
#define NCAND 16
#define NPRE 32

#define QSC  23.090909f         // 127/5.5
#define DEQ2 (2.0f/(QSC*QSC))

#define SCP 66                  // scores pitch (words), float2-aligned
#define SM_A   0                // 64 x 512 = 32768
#define SM_B0  32768            // 64 x 512
#define SM_B1  65536
#define SM_SC  98304            // scores[64][66] fp32 = 16896
#define SMEM_SC_TOTAL 115200    // fits 2 CTAs/SM (2*(115200+1024) <= 233472)

__device__ int8_t g_Xq[(size_t)M_Q*KDIM];
__device__ int8_t g_DBq[(size_t)NPAD*KDIM];
__device__ float g_dbnorm[NPAD];
__device__ float g_cv[(size_t)M_Q*NSEG*NCAND];
__device__ int   g_ci[(size_t)M_Q*NSEG*NCAND];

__device__ __forceinline__ unsigned smem_u32(const void* p) {
    unsigned a;
    asm("{ .reg .u64 t; cvta.to.shared.u64 t, %1; cvt.u32.u64 %0, t; }"
        : "=r"(a) : "l"(p));
    return a;
}
__device__ __forceinline__ void cp16(unsigned dsts, const void* src) {
    asm volatile("cp.async.cg.shared.global [%0], [%1], 16;\n" :: "r"(dsts), "l"(src));
}
__device__ __forceinline__ void ldsm4(unsigned& r0, unsigned& r1, unsigned& r2,
                                      unsigned& r3, unsigned addr) {
    asm volatile("ldmatrix.sync.aligned.m8n8.x4.shared.b16 {%0,%1,%2,%3}, [%4];"
                 : "=r"(r0), "=r"(r1), "=r"(r2), "=r"(r3) : "r"(addr));
}
__device__ __forceinline__ void imma16832(int* c,
    unsigned a0, unsigned a1, unsigned a2, unsigned a3, unsigned b0, unsigned b1) {
    asm volatile("mma.sync.aligned.m16n8k32.row.col.s32.s8.s8.s32 "
        "{%0,%1,%2,%3}, {%4,%5,%6,%7}, {%8,%9}, {%0,%1,%2,%3};\n"
        : "+r"(c[0]), "+r"(c[1]), "+r"(c[2]), "+r"(c[3])
        : "r"(a0), "r"(a1), "r"(a2), "r"(a3), "r"(b0), "r"(b1));
}

// ---------------- prep ----------------
__global__ void conv_x_kernel(const float* __restrict__ x) {
    int i = blockIdx.x*blockDim.x + threadIdx.x;
    if (i < M_Q*KDIM) {
        float v = fminf(fmaxf(x[i], -5.5f), 5.5f);
        g_Xq[i] = (int8_t)__float2int_rn(v * QSC);
    }
}

__global__ void conv_db_kernel(const float* __restrict__ db) {
    int r = blockIdx.x;
    int tid = threadIdx.x;      // 128
    __shared__ float wsum[4];
    if (r < NDB) {
        const float* row = db + (size_t)r*KDIM;
        float acc = 0.f;
        for (int k = tid; k < KDIM; k += 128) {
            float v = row[k];
            acc += v*v;
            float c = fminf(fmaxf(v, -5.5f), 5.5f);
            g_DBq[(size_t)r*KDIM + k] = (int8_t)__float2int_rn(c * QSC);
        }
        #pragma unroll
        for (int o = 16; o; o >>= 1) acc += __shfl_xor_sync(0xffffffffu, acc, o);
        if ((tid & 31) == 0) wsum[tid >> 5] = acc;
        __syncthreads();
        if (tid == 0) g_dbnorm[r] = wsum[0]+wsum[1]+wsum[2]+wsum[3];
    } else {
        for (int k = tid; k < KDIM; k += 128)
            g_DBq[(size_t)r*KDIM + k] = 0;
        if (tid == 0) g_dbnorm[r] = __int_as_float(0x7f800000);
    }
}

// ---------------- register-resident sorted top-16 insert (static indices) ----------------
__device__ __forceinline__ void ins16(float v, int id, float* tv, int* ti) {
    if (v < tv[NCAND-1]) {
        #pragma unroll
        for (int p = NCAND-1; p >= 1; --p) {
            bool keep = tv[p] <= v;
            bool shft = tv[p-1] > v;
            float nv = keep ? tv[p] : (shft ? tv[p-1] : v);
            int   ni = keep ? ti[p] : (shft ? ti[p-1] : id);
            tv[p] = nv; ti[p] = ni;
        }
        if (tv[0] > v) { tv[0] = v; ti[0] = id; }
    }
}

// thread scans its 16-col slice of one query
__device__ __forceinline__ void sel16(const float* srow, const float* nrm,
                                      int base, float* tv, int* ti) {
    float nv[16];
    #pragma unroll
    for (int t = 0; t < 4; ++t) {
        float4 n = __ldg((const float4*)nrm + t);
        nv[t*4] = n.x; nv[t*4+1] = n.y; nv[t*4+2] = n.z; nv[t*4+3] = n.w;
    }
    #pragma unroll
    for (int j2 = 0; j2 < 8; ++j2) {
        float2 s = *(const float2*)(srow + j2*2);
        ins16(nv[j2*2]   - DEQ2*s.x, base + j2*2,     tv, ti);
        ins16(nv[j2*2+1] - DEQ2*s.y, base + j2*2 + 1, tv, ti);
    }
}

__global__ __launch_bounds__(256, 2)
void score_topk_kernel(int seg0) {
    extern __shared__ char sm[];
    const int tid = threadIdx.x;
    const int warp = tid >> 5, lane = tid & 31;
    const int wm = warp >> 2, wn = warp & 3;   // 2m x 4n warps, tile 32m x 16n
    const int m0 = blockIdx.x * BM;
    const int seg = seg0 + blockIdx.y;
    const int segbase = seg * SEGROWS;
    const unsigned sbase = smem_u32(sm);
    float* scS = (float*)(sm + SM_SC);

    // prologue: A tile (64x512 int8, swizzled rows) + B chunk 0
    for (int i = tid; i < BM*32; i += 256) {
        int r = i >> 5, c16 = i & 31;
        cp16(sbase + SM_A + r*512 + ((c16 ^ (r & 7))*16),
             g_Xq + (size_t)(m0 + r)*KDIM + c16*16);
    }
    for (int i = tid; i < BN*32; i += 256) {
        int r = i >> 5, c16 = i & 31;
        cp16(sbase + SM_B0 + r*512 + ((c16 ^ (r & 7))*16),
             g_DBq + (size_t)(segbase + r)*KDIM + c16*16);
    }
    asm volatile("cp.async.commit_group;\n" ::: "memory");

    float tv[NCAND]; int ti[NCAND];
    #pragma unroll
    for (int i = 0; i < NCAND; ++i) { tv[i] = __int_as_float(0x7f800000); ti[i] = -1; }

    // LDSM lane constants (swizzled 512B rows)
    const unsigned aRow0 = sbase + SM_A + (unsigned)((wm*32 + (lane & 15))*512);
    const unsigned aSel  = (unsigned)(lane >> 4);
    const unsigned lXor  = (unsigned)(lane & 7);
    const int rB = wn*16 + ((lane >> 4) << 3) + (lane & 7);
    const unsigned bRowOff = (unsigned)(rB*512);
    const unsigned bSel = (unsigned)((lane >> 3) & 1);

    // selection slice constants: query row tid>>2, cols (tid&3)*16
    const int qrow = tid >> 2, c0 = (tid & 3) * 16;
    const float* srow = scS + qrow*SCP + c0;

    for (int c = 0; c < NCHUNKS; ++c) {
        asm volatile("cp.async.wait_group 0;\n" ::: "memory");
        __syncthreads();          // B[c] ready; epilogue(c-1) visible

        if (c + 1 < NCHUNKS) {    // prefetch B[c+1]
            unsigned nxt = sbase + ((c & 1) ? SM_B0 : SM_B1);
            const int8_t* src = g_DBq + (size_t)(segbase + (c+1)*BN)*KDIM;
            for (int i = tid; i < BN*32; i += 256) {
                int r = i >> 5, c16 = i & 31;
                cp16(nxt + r*512 + ((c16 ^ (r & 7))*16), src + (size_t)r*KDIM + c16*16);
            }
            asm volatile("cp.async.commit_group;\n" ::: "memory");
        }

        int acc[2][2][4];
        #pragma unroll
        for (int mt = 0; mt < 2; ++mt)
            #pragma unroll
            for (int nt = 0; nt < 2; ++nt)
                #pragma unroll
                for (int e = 0; e < 4; ++e) acc[mt][nt][e] = 0;

        const unsigned Bsm = sbase + ((c & 1) ? SM_B1 : SM_B0) + bRowOff;
        #pragma unroll 8
        for (int ks = 0; ks < 16; ++ks) {
            unsigned a0[4], a1[4], b[4];
            unsigned aoff = (((unsigned)(ks*2) + aSel) ^ lXor) << 4;
            unsigned boff = (((unsigned)(ks*2) + bSel) ^ lXor) << 4;
            ldsm4(a0[0], a0[1], a0[2], a0[3], aRow0 + aoff);
            ldsm4(a1[0], a1[1], a1[2], a1[3], aRow0 + 16*512 + aoff);
            ldsm4(b[0], b[1], b[2], b[3], Bsm + boff);
            imma16832(acc[0][0], a0[0], a0[1], a0[2], a0[3], b[0], b[1]);
            imma16832(acc[0][1], a0[0], a0[1], a0[2], a0[3], b[2], b[3]);
            imma16832(acc[1][0], a1[0], a1[1], a1[2], a1[3], b[0], b[1]);
            imma16832(acc[1][1], a1[0], a1[1], a1[2], a1[3], b[2], b[3]);
        }

        // all 256 threads: select slice of chunk c-1
        if (c > 0)
            sel16(srow, g_dbnorm + segbase + (c-1)*BN + c0,
                  segbase + (c-1)*BN + c0, tv, ti);
        __syncthreads();          // selection done; scores buffer free

        // epilogue: float2 stores, pitch 66
        #pragma unroll
        for (int mt = 0; mt < 2; ++mt)
            #pragma unroll
            for (int nt = 0; nt < 2; ++nt) {
                int col = wn*16 + nt*8 + ((lane & 3) << 1);
                int r0 = wm*32 + mt*16 + (lane >> 2);
                *(float2*)(scS + r0*SCP + col) =
                    make_float2((float)acc[mt][nt][0], (float)acc[mt][nt][1]);
                *(float2*)(scS + (r0 + 8)*SCP + col) =
                    make_float2((float)acc[mt][nt][2], (float)acc[mt][nt][3]);
            }
    }
    __syncthreads();
    sel16(srow, g_dbnorm + segbase + (NCHUNKS-1)*BN + c0,
          segbase + (NCHUNKS-1)*BN + c0, tv, ti);

    // merge the 4 slices of each query via shuffles (group = 4 lanes)
    const unsigned fm = 0xffffffffu;
    #pragma unroll
    for (int src = 1; src < 4; ++src) {
        #pragma unroll
        for (int k = 0; k < NCAND; ++k) {
            float v = __shfl_sync(fm, tv[k], (lane & ~3) + src);
            int  id = __shfl_sync(fm, ti[k], (lane & ~3) + src);
            if ((lane & 3) == 0) ins16(v, id, tv, ti);
        }
    }
    if ((tid & 3) == 0) {
        size_t base = ((size_t)(m0 + qrow)*NSEG + seg)*NCAND;
        #pragma unroll
        for (int i = 0; i < NCAND; ++i) { g_cv[base + i] = tv[i]; g_ci[base + i] = ti[i]; }
    }
}

// ---------------- LLE (unchanged, proven) ----------------
__global__ __launch_bounds__(128)
void lle_kernel(const float* __restrict__ x, const float* __restrict__ db,
                float* __restrict__ out) {
    __shared__ float xs[512];
    __shared__ float nb[10*520];
    __shared__ float cv[128];
    __shared__ int   ci[128];
    __shared__ int   psel[NPRE];
    __shared__ float pd[NPRE];
    __shared__ float G[9][10];
    __shared__ float w[9];
    __shared__ int   sel[10];

    const int q = blockIdx.x, tid = threadIdx.x;
    const int warp = tid >> 5, lane = tid & 31;
    size_t cb = (size_t)q*NSEG*NCAND;
    cv[tid] = g_cv[cb + tid];
    ci[tid] = g_ci[cb + tid];
    for (int n = tid; n < 512; n += 128) xs[n] = x[(size_t)q*512 + n];
    __syncthreads();

    if (tid == 0) {
        float bv[NPRE]; int bi[NPRE];
        #pragma unroll
        for (int i = 0; i < NPRE; ++i) { bv[i] = __int_as_float(0x7f800000); bi[i] = 0x7fffffff; }
        for (int c = 0; c < 128; ++c) {
            float v = cv[c]; int id = ci[c];
            if (v < bv[NPRE-1]) {
                int p = NPRE-1;
                while (p > 0 && bv[p-1] > v) { bv[p] = bv[p-1]; bi[p] = bi[p-1]; --p; }
                bv[p] = v; bi[p] = id;
            }
        }
        #pragma unroll
        for (int i = 0; i < NPRE; ++i) psel[i] = bi[i];
    }
    __syncthreads();

    for (int c = warp*8; c < warp*8 + 8; ++c) {
        const float* row = db + (size_t)psel[c]*512;
        float acc = 0.f;
        #pragma unroll
        for (int j = 0; j < 16; ++j) {
            int n = lane + 32*j;
            float v = row[n] - xs[n];
            acc = fmaf(v, v, acc);
        }
        #pragma unroll
        for (int o = 16; o; o >>= 1) acc += __shfl_xor_sync(0xffffffffu, acc, o);
        if (lane == 0) pd[c] = acc;
    }
    __syncthreads();

    if (tid == 0) {
        float bv[10]; int bi[10];
        #pragma unroll
        for (int i = 0; i < 10; ++i) { bv[i] = __int_as_float(0x7f800000); bi[i] = 0x7fffffff; }
        for (int c = 0; c < NPRE; ++c) {
            float v = pd[c]; int id = psel[c];
            if (v < bv[9] || (v == bv[9] && id < bi[9])) {
                int p = 9;
                while (p > 0 && (bv[p-1] > v || (bv[p-1] == v && bi[p-1] > id))) {
                    bv[p] = bv[p-1]; bi[p] = bi[p-1]; --p;
                }
                bv[p] = v; bi[p] = id;
            }
        }
        #pragma unroll
        for (int i = 0; i < 10; ++i) sel[i] = bi[i];
    }
    __syncthreads();

    for (int r = 0; r < 10; ++r) {
        const float* row = db + (size_t)sel[r]*512;
        for (int n = tid; n < 512; n += 128) nb[r*520 + n] = row[n];
    }
    __syncthreads();

    if (tid < 90) {
        float accv = 0.f;
        if (tid < 81) {
            int i = tid / 9, j = tid % 9;
            const float* ai = nb + (i+1)*520;
            const float* aj = nb + (j+1)*520;
            for (int n = 0; n < 512; ++n) {
                float f0 = nb[n];
                accv += (ai[n]-f0)*(aj[n]-f0);
            }
            G[i][j] = accv;
        } else {
            int i = tid - 81;
            const float* ai = nb + (i+1)*520;
            for (int n = 0; n < 512; ++n) {
                float f0 = nb[n];
                accv += (ai[n]-f0)*(xs[n]-f0);
            }
            G[i][9] = accv;
        }
    }
    __syncthreads();

    if (tid == 0) {
        for (int k = 0; k < 9; ++k) {
            int p = k;
            for (int r = k+1; r < 9; ++r)
                if (fabsf(G[r][k]) > fabsf(G[p][k])) p = r;
            if (p != k)
                for (int c = k; c < 10; ++c) {
                    float t = G[k][c]; G[k][c] = G[p][c]; G[p][c] = t;
                }
            float inv = 1.f / G[k][k];
            for (int r = k+1; r < 9; ++r) {
                float f = G[r][k] * inv;
                for (int c = k; c < 10; ++c) G[r][c] -= f*G[k][c];
            }
        }
        for (int k = 8; k >= 0; --k) {
            float s = G[k][9];
            for (int c = k+1; c < 9; ++c) s -= G[k][c]*w[c];
            w[k] = s / G[k][k];
        }
    }
    __syncthreads();

    float w0 = 1.f;
    #pragma unroll
    for (int k = 0; k < 9; ++k) w0 -= w[k];
    for (int n = tid; n < 512; n += 128) {
        float fuse = w0 * nb[n];
        #pragma unroll
        for (int k = 0; k < 9; ++k) fuse += w[k]*nb[(k+1)*520 + n];
        out[(size_t)q*512 + n] = 0.2f*xs[n] + 0.8f*fuse;
    }
}

extern "C" void kernel_launch(void* const* d_in, const int* in_sizes, int n_in,
                              void* d_out, int out_size) {
    const float* x  = (const float*)d_in[0];
    const float* db = (const float*)d_in[1];
    float* out = (float*)d_out;

    cudaFuncSetAttribute(score_topk_kernel,
        cudaFuncAttributeMaxDynamicSharedMemorySize, SMEM_SC_TOTAL);

    conv_x_kernel<<<(M_Q*KDIM + 255)/256, 256>>>(x);
    conv_db_kernel<<<NPAD, 128>>>(db);
    score_topk_kernel<<<dim3(M_Q/BM, NSEG/2), 256, SMEM_SC_TOTAL>>>(0);
    score_topk_kernel<<<dim3(M_Q/BM, NSEG/2), 256, SMEM_SC_TOTAL>>>(4);  // 4th launch -> ncu
    lle_kernel<<<M_Q, 128>>>(x, db, out);
}

// round 12
// speedup vs baseline: 3.8875x; 2.0344x over previous
#include <cuda_runtime.h>
#include <cuda_bf16.h>
#include <cstdint>

#define M_Q 4096
#define KDIM 512
#define NDB 50000
#define NSEG 8
#define SEGROWS 6272
#define NPAD (NSEG*SEGROWS)
#define BM 64
#define BN 64
#define NCHUNKS (SEGROWS/BN)    // 98
#define NCAND 16

#define QSC  23.090909f         // 127/5.5
#define DEQ2 (2.0f/(QSC*QSC))

#define SCP 66
#define SM_A   0
#define SM_B0  32768
#define SM_B1  65536
#define SM_SC  98304
#define SMEM_SC_TOTAL 115200    // 2 CTAs/SM

__device__ int8_t g_Xq[(size_t)M_Q*KDIM];
__device__ int8_t g_DBq[(size_t)NPAD*KDIM];
__device__ float g_dbnorm[NPAD];
__device__ float g_cv[(size_t)M_Q*NSEG*NCAND];
__device__ int   g_ci[(size_t)M_Q*NSEG*NCAND];

__device__ __forceinline__ unsigned smem_u32(const void* p) {
    unsigned a;
    asm("{ .reg .u64 t; cvta.to.shared.u64 t, %1; cvt.u32.u64 %0, t; }"
        : "=r"(a) : "l"(p));
    return a;
}
__device__ __forceinline__ void cp16(unsigned dsts, const void* src) {
    asm volatile("cp.async.cg.shared.global [%0], [%1], 16;\n" :: "r"(dsts), "l"(src));
}
__device__ __forceinline__ void ldsm4(unsigned& r0, unsigned& r1, unsigned& r2,
                                      unsigned& r3, unsigned addr) {
    asm volatile("ldmatrix.sync.aligned.m8n8.x4.shared.b16 {%0,%1,%2,%3}, [%4];"
                 : "=r"(r0), "=r"(r1), "=r"(r2), "=r"(r3) : "r"(addr));
}
__device__ __forceinline__ void imma16832(int* c,
    unsigned a0, unsigned a1, unsigned a2, unsigned a3, unsigned b0, unsigned b1) {
    asm volatile("mma.sync.aligned.m16n8k32.row.col.s32.s8.s8.s32 "
        "{%0,%1,%2,%3}, {%4,%5,%6,%7}, {%8,%9}, {%0,%1,%2,%3};\n"
        : "+r"(c[0]), "+r"(c[1]), "+r"(c[2]), "+r"(c[3])
        : "r"(a0), "r"(a1), "r"(a2), "r"(a3), "r"(b0), "r"(b1));
}
__device__ __forceinline__ int8_t q8(float v) {
    return (int8_t)__float2int_rn(fminf(fmaxf(v, -5.5f), 5.5f) * QSC);
}

// ---------------- prep: packed char4 writes ----------------
__global__ void conv_x_kernel(const float* __restrict__ x) {
    int i = blockIdx.x*blockDim.x + threadIdx.x;      // one per 4 elems
    if (i < M_Q*KDIM/4) {
        float4 v = ((const float4*)x)[i];
        char4 p = make_char4(q8(v.x), q8(v.y), q8(v.z), q8(v.w));
        ((char4*)g_Xq)[i] = p;
    }
}

__global__ void conv_db_kernel(const float* __restrict__ db) {
    int r = blockIdx.x;
    int tid = threadIdx.x;      // 128; thread t handles elems 4t..4t+3
    __shared__ float wsum[4];
    if (r < NDB) {
        float4 v = ((const float4*)(db + (size_t)r*KDIM))[tid];
        float acc = v.x*v.x + v.y*v.y + v.z*v.z + v.w*v.w;
        ((char4*)g_DBq)[(size_t)r*128 + tid] =
            make_char4(q8(v.x), q8(v.y), q8(v.z), q8(v.w));
        #pragma unroll
        for (int o = 16; o; o >>= 1) acc += __shfl_xor_sync(0xffffffffu, acc, o);
        if ((tid & 31) == 0) wsum[tid >> 5] = acc;
        __syncthreads();
        if (tid == 0) g_dbnorm[r] = wsum[0]+wsum[1]+wsum[2]+wsum[3];
    } else {
        ((char4*)g_DBq)[(size_t)r*128 + tid] = make_char4(0,0,0,0);
        if (tid == 0) g_dbnorm[r] = __int_as_float(0x7f800000);
    }
}

// ---------------- score (byte-identical to R11 passing version) ----------------
__device__ __forceinline__ void ins16(float v, int id, float* tv, int* ti) {
    if (v < tv[NCAND-1]) {
        #pragma unroll
        for (int p = NCAND-1; p >= 1; --p) {
            bool keep = tv[p] <= v;
            bool shft = tv[p-1] > v;
            float nv = keep ? tv[p] : (shft ? tv[p-1] : v);
            int   ni = keep ? ti[p] : (shft ? ti[p-1] : id);
            tv[p] = nv; ti[p] = ni;
        }
        if (tv[0] > v) { tv[0] = v; ti[0] = id; }
    }
}

__device__ __forceinline__ void sel16(const float* srow, const float* nrm,
                                      int base, float* tv, int* ti) {
    float nv[16];
    #pragma unroll
    for (int t = 0; t < 4; ++t) {
        float4 n = __ldg((const float4*)nrm + t);
        nv[t*4] = n.x; nv[t*4+1] = n.y; nv[t*4+2] = n.z; nv[t*4+3] = n.w;
    }
    #pragma unroll
    for (int j2 = 0; j2 < 8; ++j2) {
        float2 s = *(const float2*)(srow + j2*2);
        ins16(nv[j2*2]   - DEQ2*s.x, base + j2*2,     tv, ti);
        ins16(nv[j2*2+1] - DEQ2*s.y, base + j2*2 + 1, tv, ti);
    }
}

__global__ __launch_bounds__(256, 2)
void score_topk_kernel(int seg0) {
    extern __shared__ char sm[];
    const int tid = threadIdx.x;
    const int warp = tid >> 5, lane = tid & 31;
    const int wm = warp >> 2, wn = warp & 3;
    const int m0 = blockIdx.x * BM;
    const int seg = seg0 + blockIdx.y;
    const int segbase = seg * SEGROWS;
    const unsigned sbase = smem_u32(sm);
    float* scS = (float*)(sm + SM_SC);

    for (int i = tid; i < BM*32; i += 256) {
        int r = i >> 5, c16 = i & 31;
        cp16(sbase + SM_A + r*512 + ((c16 ^ (r & 7))*16),
             g_Xq + (size_t)(m0 + r)*KDIM + c16*16);
    }
    for (int i = tid; i < BN*32; i += 256) {
        int r = i >> 5, c16 = i & 31;
        cp16(sbase + SM_B0 + r*512 + ((c16 ^ (r & 7))*16),
             g_DBq + (size_t)(segbase + r)*KDIM + c16*16);
    }
    asm volatile("cp.async.commit_group;\n" ::: "memory");

    float tv[NCAND]; int ti[NCAND];
    #pragma unroll
    for (int i = 0; i < NCAND; ++i) { tv[i] = __int_as_float(0x7f800000); ti[i] = -1; }

    const unsigned aRow0 = sbase + SM_A + (unsigned)((wm*32 + (lane & 15))*512);
    const unsigned aSel  = (unsigned)(lane >> 4);
    const unsigned lXor  = (unsigned)(lane & 7);
    const int rB = wn*16 + ((lane >> 4) << 3) + (lane & 7);
    const unsigned bRowOff = (unsigned)(rB*512);
    const unsigned bSel = (unsigned)((lane >> 3) & 1);

    const int qrow = tid >> 2, c0 = (tid & 3) * 16;
    const float* srow = scS + qrow*SCP + c0;

    for (int c = 0; c < NCHUNKS; ++c) {
        asm volatile("cp.async.wait_group 0;\n" ::: "memory");
        __syncthreads();

        if (c + 1 < NCHUNKS) {
            unsigned nxt = sbase + ((c & 1) ? SM_B0 : SM_B1);
            const int8_t* src = g_DBq + (size_t)(segbase + (c+1)*BN)*KDIM;
            for (int i = tid; i < BN*32; i += 256) {
                int r = i >> 5, c16 = i & 31;
                cp16(nxt + r*512 + ((c16 ^ (r & 7))*16), src + (size_t)r*KDIM + c16*16);
            }
            asm volatile("cp.async.commit_group;\n" ::: "memory");
        }

        int acc[2][2][4];
        #pragma unroll
        for (int mt = 0; mt < 2; ++mt)
            #pragma unroll
            for (int nt = 0; nt < 2; ++nt)
                #pragma unroll
                for (int e = 0; e < 4; ++e) acc[mt][nt][e] = 0;

        const unsigned Bsm = sbase + ((c & 1) ? SM_B1 : SM_B0) + bRowOff;
        #pragma unroll 8
        for (int ks = 0; ks < 16; ++ks) {
            unsigned a0[4], a1[4], b[4];
            unsigned aoff = (((unsigned)(ks*2) + aSel) ^ lXor) << 4;
            unsigned boff = (((unsigned)(ks*2) + bSel) ^ lXor) << 4;
            ldsm4(a0[0], a0[1], a0[2], a0[3], aRow0 + aoff);
            ldsm4(a1[0], a1[1], a1[2], a1[3], aRow0 + 16*512 + aoff);
            ldsm4(b[0], b[1], b[2], b[3], Bsm + boff);
            imma16832(acc[0][0], a0[0], a0[1], a0[2], a0[3], b[0], b[1]);
            imma16832(acc[0][1], a0[0], a0[1], a0[2], a0[3], b[2], b[3]);
            imma16832(acc[1][0], a1[0], a1[1], a1[2], a1[3], b[0], b[1]);
            imma16832(acc[1][1], a1[0], a1[1], a1[2], a1[3], b[2], b[3]);
        }

        if (c > 0)
            sel16(srow, g_dbnorm + segbase + (c-1)*BN + c0,
                  segbase + (c-1)*BN + c0, tv, ti);
        __syncthreads();

        #pragma unroll
        for (int mt = 0; mt < 2; ++mt)
            #pragma unroll
            for (int nt = 0; nt < 2; ++nt) {
                int col = wn*16 + nt*8 + ((lane & 3) << 1);
                int r0 = wm*32 + mt*16 + (lane >> 2);
                *(float2*)(scS + r0*SCP + col) =
                    make_float2((float)acc[mt][nt][0], (float)acc[mt][nt][1]);
                *(float2*)(scS + (r0 + 8)*SCP + col) =
                    make_float2((float)acc[mt][nt][2], (float)acc[mt][nt][3]);
            }
    }
    __syncthreads();
    sel16(srow, g_dbnorm + segbase + (NCHUNKS-1)*BN + c0,
          segbase + (NCHUNKS-1)*BN + c0, tv, ti);

    const unsigned fm = 0xffffffffu;
    #pragma unroll
    for (int src = 1; src < 4; ++src) {
        #pragma unroll
        for (int k = 0; k < NCAND; ++k) {
            float v = __shfl_sync(fm, tv[k], (lane & ~3) + src);
            int  id = __shfl_sync(fm, ti[k], (lane & ~3) + src);
            if ((lane & 3) == 0) ins16(v, id, tv, ti);
        }
    }
    if ((tid & 3) == 0) {
        size_t base = ((size_t)(m0 + qrow)*NSEG + seg)*NCAND;
        #pragma unroll
        for (int i = 0; i < NCAND; ++i) { g_cv[base + i] = tv[i]; g_ci[base + i] = ti[i]; }
    }
}

// ---------------- LLE: exact rescore of ALL 128 candidates + parallel top-10 ----------------
__global__ __launch_bounds__(128)
void lle_kernel(const float* __restrict__ x, const float* __restrict__ db,
                float* __restrict__ out) {
    __shared__ float xs[512];
    __shared__ float nb[10*520];
    __shared__ float pd[128];
    __shared__ int   ci[128];
    __shared__ float G[9][10];
    __shared__ float w[9];
    __shared__ int   sel[10];

    const int q = blockIdx.x, tid = threadIdx.x;
    const int warp = tid >> 5, lane = tid & 31;
    ci[tid] = g_ci[(size_t)q*NSEG*NCAND + tid];
    for (int n = tid; n < 512; n += 128) xs[n] = x[(size_t)q*512 + n];
    __syncthreads();

    // exact fp32 rescore of all 128 candidates (warp handles 32)
    for (int c = warp*32; c < warp*32 + 32; ++c) {
        const float* row = db + (size_t)ci[c]*512;
        float acc = 0.f;
        #pragma unroll
        for (int j = 0; j < 16; ++j) {
            int n = lane + 32*j;
            float v = row[n] - xs[n];
            acc = fmaf(v, v, acc);
        }
        #pragma unroll
        for (int o = 16; o; o >>= 1) acc += __shfl_xor_sync(0xffffffffu, acc, o);
        if (lane == 0) pd[c] = acc;
    }
    __syncthreads();

    // warp 0: parallel exact top-10 by (d asc, idx asc) via 64-bit key min-reduce
    if (warp == 0) {
        unsigned long long k[4];
        #pragma unroll
        for (int t = 0; t < 4; ++t) {
            int c = lane + 32*t;
            k[t] = ((unsigned long long)__float_as_uint(pd[c]) << 32)
                 | (unsigned)ci[c];
        }
        for (int r = 0; r < 10; ++r) {
            unsigned long long m = k[0];
            #pragma unroll
            for (int t = 1; t < 4; ++t) m = (k[t] < m) ? k[t] : m;
            #pragma unroll
            for (int o = 16; o; o >>= 1) {
                unsigned long long v = __shfl_xor_sync(0xffffffffu, m, o);
                m = (v < m) ? v : m;
            }
            #pragma unroll
            for (int t = 0; t < 4; ++t)
                if (k[t] == m) k[t] = ~0ull;      // keys unique (distinct idx)
            if (lane == 0) sel[r] = (int)(m & 0xffffffffu);
        }
    }
    __syncthreads();

    for (int r = 0; r < 10; ++r) {
        const float* row = db + (size_t)sel[r]*512;
        for (int n = tid; n < 512; n += 128) nb[r*520 + n] = row[n];
    }
    __syncthreads();

    if (tid < 90) {   // Gram
        float accv = 0.f;
        if (tid < 81) {
            int i = tid / 9, j = tid % 9;
            const float* ai = nb + (i+1)*520;
            const float* aj = nb + (j+1)*520;
            for (int n = 0; n < 512; ++n) {
                float f0 = nb[n];
                accv += (ai[n]-f0)*(aj[n]-f0);
            }
            G[i][j] = accv;
        } else {
            int i = tid - 81;
            const float* ai = nb + (i+1)*520;
            for (int n = 0; n < 512; ++n) {
                float f0 = nb[n];
                accv += (ai[n]-f0)*(xs[n]-f0);
            }
            G[i][9] = accv;
        }
    }
    __syncthreads();

    if (tid == 0) {   // 9x9 Gauss, partial pivoting
        for (int k2 = 0; k2 < 9; ++k2) {
            int p = k2;
            for (int r = k2+1; r < 9; ++r)
                if (fabsf(G[r][k2]) > fabsf(G[p][k2])) p = r;
            if (p != k2)
                for (int c = k2; c < 10; ++c) {
                    float t = G[k2][c]; G[k2][c] = G[p][c]; G[p][c] = t;
                }
            float inv = 1.f / G[k2][k2];
            for (int r = k2+1; r < 9; ++r) {
                float f = G[r][k2] * inv;
                for (int c = k2; c < 10; ++c) G[r][c] -= f*G[k2][c];
            }
        }
        for (int k2 = 8; k2 >= 0; --k2) {
            float s = G[k2][9];
            for (int c = k2+1; c < 9; ++c) s -= G[k2][c]*w[c];
            w[k2] = s / G[k2][k2];
        }
    }
    __syncthreads();

    float w0 = 1.f;
    #pragma unroll
    for (int k2 = 0; k2 < 9; ++k2) w0 -= w[k2];
    for (int n = tid; n < 512; n += 128) {
        float fuse = w0 * nb[n];
        #pragma unroll
        for (int k2 = 0; k2 < 9; ++k2) fuse += w[k2]*nb[(k2+1)*520 + n];
        out[(size_t)q*512 + n] = 0.2f*xs[n] + 0.8f*fuse;
    }
}

extern "C" void kernel_launch(void* const* d_in, const int* in_sizes, int n_in,
                              void* d_out, int out_size) {
    const float* x  = (const float*)d_in[0];
    const float* db = (const float*)d_in[1];
    float* out = (float*)d_out;

    cudaFuncSetAttribute(score_topk_kernel,
        cudaFuncAttributeMaxDynamicSharedMemorySize, SMEM_SC_TOTAL);

    conv_x_kernel<<<(M_Q*KDIM/4 + 255)/256, 256>>>(x);
    conv_db_kernel<<<NPAD, 128>>>(db);
    score_topk_kernel<<<dim3(M_Q/BM, NSEG/2), 256, SMEM_SC_TOTAL>>>(0);
    score_topk_kernel<<<dim3(M_Q/BM, NSEG/2), 256, SMEM_SC_TOTAL>>>(4);
    lle_kernel<<<M_Q, 128>>>(x, db, out);
}

// round 13
// speedup vs baseline: 4.5122x; 1.1607x over previous
#include <cuda_runtime.h>
#include <cuda_bf16.h>
#include <cstdint>

#define M_Q 4096
#define KDIM 512
#define NDB 50000
#define NSEG 8
#define SEGROWS 6272
#define NPAD (NSEG*SEGROWS)
#define BM 64
#define BN 32
#define NCHUNKS (SEGROWS/BN)    // 196
#define NSEL 10
#define NC_LLE (NSEG*NSEL)      // 80

#define QSC  23.090909f         // 127/5.5
#define DEQ2 (2.0f/(QSC*QSC))

#define SCP 34                  // scores pitch (words)
#define SM_A   0                // 64 x 512 = 32768
#define SM_B0  32768            // 32 x 512 = 16384
#define SM_B1  49152
#define SM_SC  65536            // scores[64][34] fp32 = 8704
#define SMEM_SC_TOTAL 74240     // 3 CTAs/SM: 3*(74240+1024) = 225792 <= 233472

__device__ int8_t g_Xq[(size_t)M_Q*KDIM];
__device__ int8_t g_DBq[(size_t)NPAD*KDIM];
__device__ float g_dbnorm[NPAD];
__device__ int   g_ci[(size_t)M_Q*NC_LLE];

__device__ __forceinline__ unsigned smem_u32(const void* p) {
    unsigned a;
    asm("{ .reg .u64 t; cvta.to.shared.u64 t, %1; cvt.u32.u64 %0, t; }"
        : "=r"(a) : "l"(p));
    return a;
}
__device__ __forceinline__ void cp16(unsigned dsts, const void* src) {
    asm volatile("cp.async.cg.shared.global [%0], [%1], 16;\n" :: "r"(dsts), "l"(src));
}
__device__ __forceinline__ void ldsm4(unsigned& r0, unsigned& r1, unsigned& r2,
                                      unsigned& r3, unsigned addr) {
    asm volatile("ldmatrix.sync.aligned.m8n8.x4.shared.b16 {%0,%1,%2,%3}, [%4];"
                 : "=r"(r0), "=r"(r1), "=r"(r2), "=r"(r3) : "r"(addr));
}
__device__ __forceinline__ void imma16832(int* c,
    unsigned a0, unsigned a1, unsigned a2, unsigned a3, unsigned b0, unsigned b1) {
    asm volatile("mma.sync.aligned.m16n8k32.row.col.s32.s8.s8.s32 "
        "{%0,%1,%2,%3}, {%4,%5,%6,%7}, {%8,%9}, {%0,%1,%2,%3};\n"
        : "+r"(c[0]), "+r"(c[1]), "+r"(c[2]), "+r"(c[3])
        : "r"(a0), "r"(a1), "r"(a2), "r"(a3), "r"(b0), "r"(b1));
}
__device__ __forceinline__ int8_t q8(float v) {
    return (int8_t)__float2int_rn(fminf(fmaxf(v, -5.5f), 5.5f) * QSC);
}

// ---------------- prep ----------------
__global__ void conv_x_kernel(const float* __restrict__ x) {
    int i = blockIdx.x*blockDim.x + threadIdx.x;
    if (i < M_Q*KDIM/4) {
        float4 v = ((const float4*)x)[i];
        ((char4*)g_Xq)[i] = make_char4(q8(v.x), q8(v.y), q8(v.z), q8(v.w));
    }
}

// warp-per-row, 8 rows per 256-thread block, shuffle-only norm
__global__ void conv_db_kernel(const float* __restrict__ db) {
    int r = blockIdx.x*8 + (threadIdx.x >> 5);
    int lane = threadIdx.x & 31;
    if (r < NDB) {
        const float4* row4 = (const float4*)(db + (size_t)r*KDIM);
        float acc = 0.f;
        #pragma unroll
        for (int k = 0; k < 4; ++k) {
            int idx = lane + 32*k;
            float4 v = row4[idx];
            acc += v.x*v.x + v.y*v.y + v.z*v.z + v.w*v.w;
            ((char4*)g_DBq)[(size_t)r*128 + idx] =
                make_char4(q8(v.x), q8(v.y), q8(v.z), q8(v.w));
        }
        #pragma unroll
        for (int o = 16; o; o >>= 1) acc += __shfl_xor_sync(0xffffffffu, acc, o);
        if (lane == 0) g_dbnorm[r] = acc;
    } else {
        #pragma unroll
        for (int k = 0; k < 4; ++k)
            ((char4*)g_DBq)[(size_t)r*128 + lane + 32*k] = make_char4(0,0,0,0);
        if (lane == 0) g_dbnorm[r] = __int_as_float(0x7f800000);
    }
}

// ---------------- register sorted top-10 (static indices, provably safe) ----------------
__device__ __forceinline__ void ins10(float v, int id, float* tv, int* ti) {
    if (v < tv[NSEL-1]) {
        #pragma unroll
        for (int p = NSEL-1; p >= 1; --p) {
            bool keep = tv[p] <= v;
            bool shft = tv[p-1] > v;
            float nv = keep ? tv[p] : (shft ? tv[p-1] : v);
            int   ni = keep ? ti[p] : (shft ? ti[p-1] : id);
            tv[p] = nv; ti[p] = ni;
        }
        if (tv[0] > v) { tv[0] = v; ti[0] = id; }
    }
}

__device__ __forceinline__ void sel8(const float* srow, const float* nrm,
                                     int base, float* tv, int* ti) {
    float4 n0 = __ldg((const float4*)nrm);
    float4 n1 = __ldg((const float4*)nrm + 1);
    float nv[8] = {n0.x, n0.y, n0.z, n0.w, n1.x, n1.y, n1.z, n1.w};
    #pragma unroll
    for (int j2 = 0; j2 < 4; ++j2) {
        float2 s = *(const float2*)(srow + j2*2);
        ins10(nv[j2*2]   - DEQ2*s.x, base + j2*2,     tv, ti);
        ins10(nv[j2*2+1] - DEQ2*s.y, base + j2*2 + 1, tv, ti);
    }
}

__global__ __launch_bounds__(256, 3)
void score_topk_kernel(int seg0) {
    extern __shared__ char sm[];
    const int tid = threadIdx.x;
    const int warp = tid >> 5, lane = tid & 31;
    const int wm = warp >> 1, wn = warp & 1;   // 4m x 2n warps, tile 16m x 16n
    const int m0 = blockIdx.x * BM;
    const int seg = seg0 + blockIdx.y;
    const int segbase = seg * SEGROWS;
    const unsigned sbase = smem_u32(sm);
    float* scS = (float*)(sm + SM_SC);

    // per-thread fixed copy slots: rows r0+8k, col group c16
    const int r0c = tid >> 5, c16 = tid & 31;
    const unsigned xoff = (unsigned)((c16 ^ (r0c & 7)) << 4);
    const unsigned smoA = (unsigned)(r0c*512) + xoff;

    // prologue: A tile (8 cps) + B chunk 0 (4 cps)
    {
        const int8_t* gA = g_Xq + (size_t)(m0 + r0c)*KDIM + c16*16;
        #pragma unroll
        for (int k = 0; k < 8; ++k)
            cp16(sbase + SM_A + smoA + k*4096, gA + (size_t)k*4096);
        const int8_t* gB = g_DBq + (size_t)(segbase + r0c)*KDIM + c16*16;
        #pragma unroll
        for (int k = 0; k < 4; ++k)
            cp16(sbase + SM_B0 + smoA + k*4096, gB + (size_t)k*4096);
    }
    asm volatile("cp.async.commit_group;\n" ::: "memory");

    float tv[NSEL]; int ti[NSEL];
    #pragma unroll
    for (int i = 0; i < NSEL; ++i) { tv[i] = __int_as_float(0x7f800000); ti[i] = -1; }

    // LDSM lane constants
    const unsigned aRow0 = sbase + SM_A + (unsigned)((wm*16 + (lane & 15))*512);
    const unsigned aSel  = (unsigned)(lane >> 4);
    const unsigned lXor  = (unsigned)(lane & 7);
    const unsigned bRowOff = (unsigned)((wn*16 + ((lane >> 4) << 3) + (lane & 7))*512);
    const unsigned bSel = (unsigned)((lane >> 3) & 1);

    // selection slice: query row tid>>2, cols (tid&3)*8
    const int qrow = tid >> 2, c0 = (tid & 3) * 8;
    const float* srow = scS + qrow*SCP + c0;
    const float* nrm0 = g_dbnorm + segbase + c0;

    // epilogue base
    float* eDst = scS + (wm*16 + (lane >> 2))*SCP + wn*16 + (lane & 3)*2;

    // incremental prefetch pointer (chunk 1 base)
    const int8_t* gPre = g_DBq + (size_t)(segbase + BN + r0c)*KDIM + c16*16;

    for (int c = 0; c < NCHUNKS; ++c) {
        asm volatile("cp.async.wait_group 0;\n" ::: "memory");
        __syncthreads();          // B[c] ready; epilogue(c-1) visible

        if (c + 1 < NCHUNKS) {
            unsigned nxt = sbase + ((c & 1) ? SM_B0 : SM_B1) + smoA;
            cp16(nxt,         gPre);
            cp16(nxt + 4096,  gPre + 4096);
            cp16(nxt + 8192,  gPre + 8192);
            cp16(nxt + 12288, gPre + 12288);
            asm volatile("cp.async.commit_group;\n" ::: "memory");
            gPre += 16384;
        }

        int acc[2][4];
        #pragma unroll
        for (int nt = 0; nt < 2; ++nt)
            #pragma unroll
            for (int e = 0; e < 4; ++e) acc[nt][e] = 0;

        const unsigned Bsm = sbase + ((c & 1) ? SM_B1 : SM_B0) + bRowOff;
        #pragma unroll 16
        for (int ks = 0; ks < 16; ++ks) {
            unsigned a[4], b[4];
            unsigned aoff = (((unsigned)(ks*2) + aSel) ^ lXor) << 4;
            unsigned boff = (((unsigned)(ks*2) + bSel) ^ lXor) << 4;
            ldsm4(a[0], a[1], a[2], a[3], aRow0 + aoff);
            ldsm4(b[0], b[1], b[2], b[3], Bsm + boff);
            imma16832(acc[0], a[0], a[1], a[2], a[3], b[0], b[1]);
            imma16832(acc[1], a[0], a[1], a[2], a[3], b[2], b[3]);
        }

        if (c > 0)
            sel8(srow, nrm0 + (c-1)*BN, segbase + (c-1)*BN + c0, tv, ti);
        __syncthreads();          // selection done; scores buffer free

        #pragma unroll
        for (int nt = 0; nt < 2; ++nt) {
            *(float2*)(eDst + nt*8) =
                make_float2((float)acc[nt][0], (float)acc[nt][1]);
            *(float2*)(eDst + 8*SCP + nt*8) =
                make_float2((float)acc[nt][2], (float)acc[nt][3]);
        }
    }
    __syncthreads();
    sel8(srow, nrm0 + (NCHUNKS-1)*BN, segbase + (NCHUNKS-1)*BN + c0, tv, ti);

    // merge 4 slices per query via shuffles
    const unsigned fm = 0xffffffffu;
    #pragma unroll
    for (int src = 1; src < 4; ++src) {
        #pragma unroll
        for (int k = 0; k < NSEL; ++k) {
            float v = __shfl_sync(fm, tv[k], (lane & ~3) + src);
            int  id = __shfl_sync(fm, ti[k], (lane & ~3) + src);
            if ((lane & 3) == 0) ins10(v, id, tv, ti);
        }
    }
    if ((tid & 3) == 0) {
        size_t base = ((size_t)(m0 + qrow)*NSEG + seg)*NSEL;
        #pragma unroll
        for (int i = 0; i < NSEL; ++i) g_ci[base + i] = ti[i];
    }
}

// ---------------- LLE: exact rescore of 80 candidates + parallel top-10 ----------------
__global__ __launch_bounds__(128)
void lle_kernel(const float* __restrict__ x, const float* __restrict__ db,
                float* __restrict__ out) {
    __shared__ float xs[512];
    __shared__ float nb[10*520];
    __shared__ float pd[NC_LLE];
    __shared__ int   ci[NC_LLE];
    __shared__ float G[9][10];
    __shared__ float w[9];
    __shared__ int   sel[10];

    const int q = blockIdx.x, tid = threadIdx.x;
    const int warp = tid >> 5, lane = tid & 31;
    if (tid < NC_LLE) ci[tid] = g_ci[(size_t)q*NC_LLE + tid];
    for (int n = tid; n < 512; n += 128) xs[n] = x[(size_t)q*512 + n];
    __syncthreads();

    // exact fp32 rescore (warp handles 20)
    for (int c = warp*20; c < warp*20 + 20; ++c) {
        const float* row = db + (size_t)ci[c]*512;
        float acc = 0.f;
        #pragma unroll
        for (int j = 0; j < 16; ++j) {
            int n = lane + 32*j;
            float v = row[n] - xs[n];
            acc = fmaf(v, v, acc);
        }
        #pragma unroll
        for (int o = 16; o; o >>= 1) acc += __shfl_xor_sync(0xffffffffu, acc, o);
        if (lane == 0) pd[c] = acc;
    }
    __syncthreads();

    // warp 0: exact top-10 by (d asc, idx asc) via 64-bit key min-reduce
    if (warp == 0) {
        unsigned long long k[3];
        #pragma unroll
        for (int t = 0; t < 3; ++t) {
            int c = lane + 32*t;
            k[t] = (c < NC_LLE)
                 ? (((unsigned long long)__float_as_uint(pd[c]) << 32) | (unsigned)ci[c])
                 : ~0ull;
        }
        for (int r = 0; r < 10; ++r) {
            unsigned long long m = k[0];
            #pragma unroll
            for (int t = 1; t < 3; ++t) m = (k[t] < m) ? k[t] : m;
            #pragma unroll
            for (int o = 16; o; o >>= 1) {
                unsigned long long v = __shfl_xor_sync(0xffffffffu, m, o);
                m = (v < m) ? v : m;
            }
            #pragma unroll
            for (int t = 0; t < 3; ++t)
                if (k[t] == m) k[t] = ~0ull;
            if (lane == 0) sel[r] = (int)(m & 0xffffffffu);
        }
    }
    __syncthreads();

    for (int r = 0; r < 10; ++r) {
        const float* row = db + (size_t)sel[r]*512;
        for (int n = tid; n < 512; n += 128) nb[r*520 + n] = row[n];
    }
    __syncthreads();

    if (tid < 90) {   // Gram
        float accv = 0.f;
        if (tid < 81) {
            int i = tid / 9, j = tid % 9;
            const float* ai = nb + (i+1)*520;
            const float* aj = nb + (j+1)*520;
            for (int n = 0; n < 512; ++n) {
                float f0 = nb[n];
                accv += (ai[n]-f0)*(aj[n]-f0);
            }
            G[i][j] = accv;
        } else {
            int i = tid - 81;
            const float* ai = nb + (i+1)*520;
            for (int n = 0; n < 512; ++n) {
                float f0 = nb[n];
                accv += (ai[n]-f0)*(xs[n]-f0);
            }
            G[i][9] = accv;
        }
    }
    __syncthreads();

    if (tid == 0) {   // 9x9 Gauss, partial pivoting
        for (int k2 = 0; k2 < 9; ++k2) {
            int p = k2;
            for (int r = k2+1; r < 9; ++r)
                if (fabsf(G[r][k2]) > fabsf(G[p][k2])) p = r;
            if (p != k2)
                for (int c = k2; c < 10; ++c) {
                    float t = G[k2][c]; G[k2][c] = G[p][c]; G[p][c] = t;
                }
            float inv = 1.f / G[k2][k2];
            for (int r = k2+1; r < 9; ++r) {
                float f = G[r][k2] * inv;
                for (int c = k2; c < 10; ++c) G[r][c] -= f*G[k2][c];
            }
        }
        for (int k2 = 8; k2 >= 0; --k2) {
            float s = G[k2][9];
            for (int c = k2+1; c < 9; ++c) s -= G[k2][c]*w[c];
            w[k2] = s / G[k2][k2];
        }
    }
    __syncthreads();

    float w0 = 1.f;
    #pragma unroll
    for (int k2 = 0; k2 < 9; ++k2) w0 -= w[k2];
    for (int n = tid; n < 512; n += 128) {
        float fuse = w0 * nb[n];
        #pragma unroll
        for (int k2 = 0; k2 < 9; ++k2) fuse += w[k2]*nb[(k2+1)*520 + n];
        out[(size_t)q*512 + n] = 0.2f*xs[n] + 0.8f*fuse;
    }
}

extern "C" void kernel_launch(void* const* d_in, const int* in_sizes, int n_in,
                              void* d_out, int out_size) {
    const float* x  = (const float*)d_in[0];
    const float* db = (const float*)d_in[1];
    float* out = (float*)d_out;

    cudaFuncSetAttribute(score_topk_kernel,
        cudaFuncAttributeMaxDynamicSharedMemorySize, SMEM_SC_TOTAL);

    conv_x_kernel<<<(M_Q*KDIM/4 + 255)/256, 256>>>(x);
    conv_db_kernel<<<NPAD/8, 256>>>(db);
    score_topk_kernel<<<dim3(M_Q/BM, NSEG/2), 256, SMEM_SC_TOTAL>>>(0);
    score_topk_kernel<<<dim3(M_Q/BM, NSEG/2), 256, SMEM_SC_TOTAL>>>(4);
    lle_kernel<<<M_Q, 128>>>(x, db, out);
}